// round 6
// baseline (speedup 1.0000x reference)
#include <cuda_runtime.h>
#include <cstdint>
#include <cstddef>

#define HID      64
#define NTHREADS 256
#define NW       8      // warps per CTA
#define MT       4      // m16 tiles per warp -> M=64 rows/warp

#define ASL  84    // A/H slice row stride (floats): 84 ≡ 20 (mod 32) -> conflict-free scalar LDS
#define WS1  144   // W1T row stride: ≡ 16 (mod 32) -> conflict-free LDS.128 (per-8-lane phases)
#define WS2  80    // W2T row stride: ≡ 16 (mod 32)

// SMEM layout (float offsets)
#define oW1 0                        // W1 permuted  [64][WS1]
#define oW2 (oW1 + 64*WS1)           // W2 permuted  [64][WS2]
#define oA  (oW2 + 64*WS2)           // per-warp slices: NW x 64 x ASL  (src->dst+eattr->H reuse)
#define oP  (oA + NW*64*ASL)         // b1,g1,be1,b2,g2,be2,W3 (7x64) + b3
#define SMEM_FLOATS (oP + 452)
#define SMEM_BYTES  (SMEM_FLOATS * 4)   // 231,184 B

__device__ __forceinline__ float tf32r(float x) {
    unsigned u;
    asm("cvt.rna.tf32.f32 %0, %1;" : "=r"(u) : "f"(x));
    return __uint_as_float(u);
}

__device__ __forceinline__ void mma_tf32(float* c,
                                         unsigned a0, unsigned a1, unsigned a2, unsigned a3,
                                         unsigned b0, unsigned b1) {
    asm volatile(
        "mma.sync.aligned.m16n8k8.row.col.f32.tf32.tf32.f32 "
        "{%0,%1,%2,%3}, {%4,%5,%6,%7}, {%8,%9}, {%0,%1,%2,%3};"
        : "+f"(c[0]), "+f"(c[1]), "+f"(c[2]), "+f"(c[3])
        : "r"(a0), "r"(a1), "r"(a2), "r"(a3), "r"(b0), "r"(b1));
}

// one K-chunk-range of GEMM accumulation over MT m16-tiles:
// buffer chunks [0, nc), weight chunks [wc0, wc0+nc)
__device__ __forceinline__ void gemm_phase(float acc[MT][8][4],
                                           const float* __restrict__ Aw,
                                           const float* __restrict__ Bw,
                                           int nc, int wc0, int ws,
                                           int g, int tg) {
    for (int c = 0; c < nc; c++) {
        const int kc = c * 16;
        const int kw = (wc0 + c) * 16;
        float4 bv[8];
        #pragma unroll
        for (int nf = 0; nf < 8; nf++)
            bv[nf] = *reinterpret_cast<const float4*>(Bw + nf * 8 * ws + kw);
        #pragma unroll
        for (int s = 0; s < 2; s++) {
            const int k = kc + s * 8 + tg;
            unsigned af[MT][4];
            #pragma unroll
            for (int mt = 0; mt < MT; mt++) {
                af[mt][0] = __float_as_uint(Aw[(g + mt * 16) * ASL + k]);
                af[mt][1] = __float_as_uint(Aw[(g + 8 + mt * 16) * ASL + k]);
                af[mt][2] = __float_as_uint(Aw[(g + mt * 16) * ASL + k + 4]);
                af[mt][3] = __float_as_uint(Aw[(g + 8 + mt * 16) * ASL + k + 4]);
            }
            #pragma unroll
            for (int nf = 0; nf < 8; nf++) {
                const unsigned bb0 = s ? __float_as_uint(bv[nf].z) : __float_as_uint(bv[nf].x);
                const unsigned bb1 = s ? __float_as_uint(bv[nf].w) : __float_as_uint(bv[nf].y);
                #pragma unroll
                for (int mt = 0; mt < MT; mt++)
                    mma_tf32(acc[mt][nf], af[mt][0], af[mt][1], af[mt][2], af[mt][3], bb0, bb1);
            }
        }
    }
}

__global__ __launch_bounds__(NTHREADS, 1)
void edgenet_kernel(const float* __restrict__ nodef,
                    const int* __restrict__ eidx,
                    const float* __restrict__ eattr,
                    const float* __restrict__ W1, const float* __restrict__ b1,
                    const float* __restrict__ g1, const float* __restrict__ be1,
                    const float* __restrict__ W2, const float* __restrict__ b2,
                    const float* __restrict__ g2, const float* __restrict__ be2,
                    const float* __restrict__ W3, const float* __restrict__ b3,
                    float* __restrict__ out, int E)
{
    extern __shared__ float sm[];
    const int tid = threadIdx.x;

    // ---- stage weights, permuted k-layout: within each 16-k chunk,
    // position p = tg*4 + j holds original k = chunk*16 + j*4 + tg ----
    for (int i = tid; i < 64 * 144; i += NTHREADS) {
        const int n = i / 144, p = i % 144;
        const int c = p >> 4, q = p & 15, tg_s = q >> 2, j = q & 3;
        const int k = c * 16 + j * 4 + tg_s;
        sm[oW1 + n * WS1 + p] = tf32r(W1[k * 64 + n]);
    }
    for (int i = tid; i < 64 * 64; i += NTHREADS) {
        const int n = i >> 6, p = i & 63;
        const int c = p >> 4, q = p & 15, tg_s = q >> 2, j = q & 3;
        const int k = c * 16 + j * 4 + tg_s;
        sm[oW2 + n * WS2 + p] = tf32r(W2[k * 64 + n]);
    }
    if (tid < 64) {
        sm[oP + tid]        = b1[tid];
        sm[oP + 64  + tid]  = g1[tid];
        sm[oP + 128 + tid]  = be1[tid];
        sm[oP + 192 + tid]  = b2[tid];
        sm[oP + 256 + tid]  = g2[tid];
        sm[oP + 320 + tid]  = be2[tid];
        sm[oP + 384 + tid]  = W3[tid];
    }
    if (tid == 0) sm[oP + 448] = b3[0];
    __syncthreads();

    const int warp = tid >> 5, lane = tid & 31;
    const int g = lane >> 2, tg = lane & 3;
    float* const Aw = &sm[oA + warp * 64 * ASL];   // warp-private 64-row slice

    const int nChunks = (E + 63) / 64;

    for (int ch = blockIdx.x * NW + warp; ch < nChunks; ch += gridDim.x * NW) {
        __syncwarp();   // prior iteration's H reads done before overwrite

        // ---------------- phase A: gather src features (k 0..63), 2 rows/lane ----------------
        #pragma unroll
        for (int rep = 0; rep < 2; rep++) {
            const int row = lane + rep * 32;
            const int e = ch * 64 + row;
            float4* a4 = reinterpret_cast<float4*>(Aw + row * ASL);
            if (e < E) {
                const int si = eidx[e];
                const float4* s4 = reinterpret_cast<const float4*>(nodef + (size_t)si * 64);
                #pragma unroll
                for (int i = 0; i < 16; i++) {
                    float4 v = s4[i];
                    v.x = tf32r(v.x); v.y = tf32r(v.y); v.z = tf32r(v.z); v.w = tf32r(v.w);
                    a4[i] = v;
                }
            } else {
                const float4 z = make_float4(0.f, 0.f, 0.f, 0.f);
                #pragma unroll
                for (int i = 0; i < 16; i++) a4[i] = z;
            }
        }
        __syncwarp();

        float acc[MT][8][4];
        #pragma unroll
        for (int mt = 0; mt < MT; mt++)
            #pragma unroll
            for (int nf = 0; nf < 8; nf++)
                acc[mt][nf][0] = acc[mt][nf][1] = acc[mt][nf][2] = acc[mt][nf][3] = 0.f;

        // GEMM1 phase A: buffer chunks 0..3 <-> W1 chunks 0..3 (k 0..63)
        gemm_phase(acc, Aw, &sm[oW1 + g * WS1 + tg * 4], 4, 0, WS1, g, tg);
        __syncwarp();

        // ---------------- phase B: gather dst (k->0..63) + eattr (k->64..79) ----------------
        #pragma unroll
        for (int rep = 0; rep < 2; rep++) {
            const int row = lane + rep * 32;
            const int e = ch * 64 + row;
            float4* a4 = reinterpret_cast<float4*>(Aw + row * ASL);
            if (e < E) {
                const int di = eidx[(size_t)E + e];
                const float4* d4 = reinterpret_cast<const float4*>(nodef + (size_t)di * 64);
                const float4* e4 = reinterpret_cast<const float4*>(eattr + (size_t)e * 16);
                #pragma unroll
                for (int i = 0; i < 16; i++) {
                    float4 v = d4[i];
                    v.x = tf32r(v.x); v.y = tf32r(v.y); v.z = tf32r(v.z); v.w = tf32r(v.w);
                    a4[i] = v;
                }
                #pragma unroll
                for (int i = 0; i < 4; i++) {
                    float4 v = e4[i];
                    v.x = tf32r(v.x); v.y = tf32r(v.y); v.z = tf32r(v.z); v.w = tf32r(v.w);
                    a4[16 + i] = v;
                }
            } else {
                const float4 z = make_float4(0.f, 0.f, 0.f, 0.f);
                #pragma unroll
                for (int i = 0; i < 20; i++) a4[i] = z;
            }
        }
        __syncwarp();

        // GEMM1 phase B: buffer chunks 0..4 <-> W1 chunks 4..8 (k 64..143)
        gemm_phase(acc, Aw, &sm[oW1 + g * WS1 + tg * 4], 5, 4, WS1, g, tg);
        __syncwarp();

        // ---------------- bias + LN1 + LeakyReLU -> H (tf32, buffer k 0..63) ----------------
        {
            float s[2 * MT], q[2 * MT];
            #pragma unroll
            for (int r = 0; r < 2 * MT; r++) { s[r] = 0.f; q[r] = 0.f; }
            #pragma unroll
            for (int mt = 0; mt < MT; mt++)
                #pragma unroll
                for (int nf = 0; nf < 8; nf++) {
                    const int col = nf * 8 + tg * 2;
                    const float bc0 = sm[oP + col], bc1 = sm[oP + col + 1];
                    float* a = acc[mt][nf];
                    a[0] += bc0; a[1] += bc1; a[2] += bc0; a[3] += bc1;
                    s[mt * 2]     += a[0] + a[1];
                    q[mt * 2]     += a[0] * a[0] + a[1] * a[1];
                    s[mt * 2 + 1] += a[2] + a[3];
                    q[mt * 2 + 1] += a[2] * a[2] + a[3] * a[3];
                }
            float mu[2 * MT], is[2 * MT];
            #pragma unroll
            for (int r = 0; r < 2 * MT; r++) {
                s[r] += __shfl_xor_sync(0xffffffffu, s[r], 1);
                s[r] += __shfl_xor_sync(0xffffffffu, s[r], 2);
                q[r] += __shfl_xor_sync(0xffffffffu, q[r], 1);
                q[r] += __shfl_xor_sync(0xffffffffu, q[r], 2);
                mu[r] = s[r] * (1.f / HID);
                is[r] = rsqrtf(fmaxf(q[r] * (1.f / HID) - mu[r] * mu[r], 0.f) + 1e-5f);
            }
            #pragma unroll
            for (int mt = 0; mt < MT; mt++) {
                float* h0p = Aw + (g + mt * 16) * ASL;
                float* h1p = Aw + (g + 8 + mt * 16) * ASL;
                const float mu0 = mu[mt * 2], is0 = is[mt * 2];
                const float mu1 = mu[mt * 2 + 1], is1 = is[mt * 2 + 1];
                #pragma unroll
                for (int nf = 0; nf < 8; nf++) {
                    const int col = nf * 8 + tg * 2;
                    const float ga0 = sm[oP + 64 + col],  ga1 = sm[oP + 64 + col + 1];
                    const float bb0 = sm[oP + 128 + col], bb1 = sm[oP + 128 + col + 1];
                    const float* a = acc[mt][nf];
                    float h00 = (a[0] - mu0) * is0 * ga0 + bb0;
                    float h01 = (a[1] - mu0) * is0 * ga1 + bb1;
                    float h10 = (a[2] - mu1) * is1 * ga0 + bb0;
                    float h11 = (a[3] - mu1) * is1 * ga1 + bb1;
                    h00 = h00 < 0.f ? 0.1f * h00 : h00;
                    h01 = h01 < 0.f ? 0.1f * h01 : h01;
                    h10 = h10 < 0.f ? 0.1f * h10 : h10;
                    h11 = h11 < 0.f ? 0.1f * h11 : h11;
                    *reinterpret_cast<float2*>(h0p + col) = make_float2(tf32r(h00), tf32r(h01));
                    *reinterpret_cast<float2*>(h1p + col) = make_float2(tf32r(h10), tf32r(h11));
                }
            }
        }
        __syncwarp();

        // ---------------- GEMM2: 64 rows x 64 x K=64 ----------------
        #pragma unroll
        for (int mt = 0; mt < MT; mt++)
            #pragma unroll
            for (int nf = 0; nf < 8; nf++)
                acc[mt][nf][0] = acc[mt][nf][1] = acc[mt][nf][2] = acc[mt][nf][3] = 0.f;
        gemm_phase(acc, Aw, &sm[oW2 + g * WS2 + tg * 4], 4, 0, WS2, g, tg);

        // ---------------- bias + LN2 + LeakyReLU + layer3 dot -> out ----------------
        {
            float s[2 * MT], q[2 * MT];
            #pragma unroll
            for (int r = 0; r < 2 * MT; r++) { s[r] = 0.f; q[r] = 0.f; }
            #pragma unroll
            for (int mt = 0; mt < MT; mt++)
                #pragma unroll
                for (int nf = 0; nf < 8; nf++) {
                    const int col = nf * 8 + tg * 2;
                    const float bc0 = sm[oP + 192 + col], bc1 = sm[oP + 192 + col + 1];
                    float* a = acc[mt][nf];
                    a[0] += bc0; a[1] += bc1; a[2] += bc0; a[3] += bc1;
                    s[mt * 2]     += a[0] + a[1];
                    q[mt * 2]     += a[0] * a[0] + a[1] * a[1];
                    s[mt * 2 + 1] += a[2] + a[3];
                    q[mt * 2 + 1] += a[2] * a[2] + a[3] * a[3];
                }
            float mu[2 * MT], is[2 * MT];
            #pragma unroll
            for (int r = 0; r < 2 * MT; r++) {
                s[r] += __shfl_xor_sync(0xffffffffu, s[r], 1);
                s[r] += __shfl_xor_sync(0xffffffffu, s[r], 2);
                q[r] += __shfl_xor_sync(0xffffffffu, q[r], 1);
                q[r] += __shfl_xor_sync(0xffffffffu, q[r], 2);
                mu[r] = s[r] * (1.f / HID);
                is[r] = rsqrtf(fmaxf(q[r] * (1.f / HID) - mu[r] * mu[r], 0.f) + 1e-5f);
            }
            float y[2 * MT];
            #pragma unroll
            for (int r = 0; r < 2 * MT; r++) y[r] = 0.f;
            #pragma unroll
            for (int mt = 0; mt < MT; mt++)
                #pragma unroll
                for (int nf = 0; nf < 8; nf++) {
                    const int col = nf * 8 + tg * 2;
                    const float ga0 = sm[oP + 256 + col], ga1 = sm[oP + 256 + col + 1];
                    const float bb0 = sm[oP + 320 + col], bb1 = sm[oP + 320 + col + 1];
                    const float w30 = sm[oP + 384 + col], w31 = sm[oP + 384 + col + 1];
                    const float* a = acc[mt][nf];
                    float h00 = (a[0] - mu[mt * 2]) * is[mt * 2] * ga0 + bb0;
                    float h01 = (a[1] - mu[mt * 2]) * is[mt * 2] * ga1 + bb1;
                    float h10 = (a[2] - mu[mt * 2 + 1]) * is[mt * 2 + 1] * ga0 + bb0;
                    float h11 = (a[3] - mu[mt * 2 + 1]) * is[mt * 2 + 1] * ga1 + bb1;
                    h00 = h00 < 0.f ? 0.1f * h00 : h00;
                    h01 = h01 < 0.f ? 0.1f * h01 : h01;
                    h10 = h10 < 0.f ? 0.1f * h10 : h10;
                    h11 = h11 < 0.f ? 0.1f * h11 : h11;
                    y[mt * 2]     += h00 * w30 + h01 * w31;
                    y[mt * 2 + 1] += h10 * w30 + h11 * w31;
                }
            #pragma unroll
            for (int r = 0; r < 2 * MT; r++) {
                y[r] += __shfl_xor_sync(0xffffffffu, y[r], 1);
                y[r] += __shfl_xor_sync(0xffffffffu, y[r], 2);
            }
            if (tg == 0) {
                const float b3s = sm[oP + 448];
                const int base = ch * 64;
                #pragma unroll
                for (int r = 0; r < 2 * MT; r++) {
                    const int eo = base + g + ((r & 1) ? 8 : 0) + (r >> 1) * 16;
                    if (eo < E) out[eo] = y[r] + b3s;
                }
            }
        }
    }
}

extern "C" void kernel_launch(void* const* d_in, const int* in_sizes, int n_in,
                              void* d_out, int out_size) {
    const float* nodef = (const float*)d_in[0];
    const int*   eidx  = (const int*)d_in[1];
    const float* eattr = (const float*)d_in[2];
    const float* W1 = (const float*)d_in[3];
    const float* b1 = (const float*)d_in[4];
    const float* g1 = (const float*)d_in[5];
    const float* be1 = (const float*)d_in[6];
    const float* W2 = (const float*)d_in[7];
    const float* b2 = (const float*)d_in[8];
    const float* g2 = (const float*)d_in[9];
    const float* be2 = (const float*)d_in[10];
    const float* W3 = (const float*)d_in[11];
    const float* b3 = (const float*)d_in[12];
    float* out = (float*)d_out;

    const int E = out_size;
    if (E <= 0) return;

    cudaFuncSetAttribute(edgenet_kernel, cudaFuncAttributeMaxDynamicSharedMemorySize, SMEM_BYTES);

    int dev = 0;
    cudaGetDevice(&dev);
    int sms = 148;
    cudaDeviceGetAttribute(&sms, cudaDevAttrMultiProcessorCount, dev);

    const int nChunks = (E + 63) / 64;
    const int ctasNeeded = (nChunks + NW - 1) / NW;
    const int grid = (ctasNeeded < sms) ? ctasNeeded : sms;

    edgenet_kernel<<<grid, NTHREADS, SMEM_BYTES>>>(
        nodef, eidx, eattr, W1, b1, g1, be1, W2, b2, g2, be2, W3, b3, out, E);
}

// round 7
// speedup vs baseline: 1.1365x; 1.1365x over previous
#include <cuda_runtime.h>
#include <cstdint>
#include <cstddef>

#define HID      64
#define NTHREADS 384
#define NW       12     // warps per CTA

#define ASL  84    // A/H slice row stride (floats): 84 ≡ 20 (mod 32) -> conflict-free scalar LDS
#define WS1  144   // W1T row stride: ≡ 16 (mod 32) -> conflict-free LDS.128 (per-8-lane phases)
#define WS2  80    // W2T row stride: ≡ 16 (mod 32)

// SMEM layout (float offsets)
#define oW1 0                        // W1 permuted  [64][WS1]
#define oW2 (oW1 + 64*WS1)           // W2 permuted  [64][WS2]
#define oA  (oW2 + 64*WS2)           // per-warp slices: NW x 32 x ASL  (src->dst+eattr->H reuse)
#define oP  (oA + NW*32*ASL)         // b1,g1,be1,b2,g2,be2,W3 (7x64) + b3
#define SMEM_FLOATS (oP + 452)
#define SMEM_BYTES  (SMEM_FLOATS * 4)   // 188,176 B

__device__ __forceinline__ float tf32r(float x) {
    unsigned u;
    asm("cvt.rna.tf32.f32 %0, %1;" : "=r"(u) : "f"(x));
    return __uint_as_float(u);
}

__device__ __forceinline__ void mma_tf32(float* c,
                                         unsigned a0, unsigned a1, unsigned a2, unsigned a3,
                                         unsigned b0, unsigned b1) {
    asm volatile(
        "mma.sync.aligned.m16n8k8.row.col.f32.tf32.tf32.f32 "
        "{%0,%1,%2,%3}, {%4,%5,%6,%7}, {%8,%9}, {%0,%1,%2,%3};"
        : "+f"(c[0]), "+f"(c[1]), "+f"(c[2]), "+f"(c[3])
        : "r"(a0), "r"(a1), "r"(a2), "r"(a3), "r"(b0), "r"(b1));
}

// one K-chunk-range of GEMM accumulation: buffer chunks [0, nc), weight chunks [wc0, wc0+nc)
__device__ __forceinline__ void gemm_phase(float acc[2][8][4],
                                           const float* __restrict__ Aw,
                                           const float* __restrict__ Bw,
                                           int nc, int wc0, int ws,
                                           int g, int tg) {
    for (int c = 0; c < nc; c++) {
        const int kc = c * 16;
        const int kw = (wc0 + c) * 16;
        float4 bv[8];
        #pragma unroll
        for (int nf = 0; nf < 8; nf++)
            bv[nf] = *reinterpret_cast<const float4*>(Bw + nf * 8 * ws + kw);
        #pragma unroll
        for (int s = 0; s < 2; s++) {
            const int k = kc + s * 8 + tg;
            unsigned a00 = __float_as_uint(Aw[g * ASL + k]);
            unsigned a01 = __float_as_uint(Aw[(g + 8) * ASL + k]);
            unsigned a02 = __float_as_uint(Aw[g * ASL + k + 4]);
            unsigned a03 = __float_as_uint(Aw[(g + 8) * ASL + k + 4]);
            unsigned a10 = __float_as_uint(Aw[(g + 16) * ASL + k]);
            unsigned a11 = __float_as_uint(Aw[(g + 24) * ASL + k]);
            unsigned a12 = __float_as_uint(Aw[(g + 16) * ASL + k + 4]);
            unsigned a13 = __float_as_uint(Aw[(g + 24) * ASL + k + 4]);
            #pragma unroll
            for (int nf = 0; nf < 8; nf++) {
                const unsigned bb0 = s ? __float_as_uint(bv[nf].z) : __float_as_uint(bv[nf].x);
                const unsigned bb1 = s ? __float_as_uint(bv[nf].w) : __float_as_uint(bv[nf].y);
                mma_tf32(acc[0][nf], a00, a01, a02, a03, bb0, bb1);
                mma_tf32(acc[1][nf], a10, a11, a12, a13, bb0, bb1);
            }
        }
    }
}

// cooperative coalesced gather of 32 node rows into the warp slice:
// 16 lanes per row (one float4 each), 2 rows per iteration, index via shfl.
__device__ __forceinline__ void gather_nodes(float* __restrict__ Aw,
                                             const float* __restrict__ nodef,
                                             int idx_lane, int base, int E, int lane) {
    const int half = lane >> 4;        // 0/1: which of the 2 rows this iteration
    const int fi = lane & 15;          // float4 index within the 64-float row
    #pragma unroll
    for (int it = 0; it < 16; it++) {
        const int row = it * 2 + half;
        const int nrow = __shfl_sync(0xffffffffu, idx_lane, row);
        float4 v = make_float4(0.f, 0.f, 0.f, 0.f);
        if (base + row < E) {
            v = *reinterpret_cast<const float4*>(nodef + (size_t)nrow * 64 + fi * 4);
            v.x = tf32r(v.x); v.y = tf32r(v.y); v.z = tf32r(v.z); v.w = tf32r(v.w);
        }
        *reinterpret_cast<float4*>(Aw + row * ASL + fi * 4) = v;
    }
}

__global__ __launch_bounds__(NTHREADS, 1)
void edgenet_kernel(const float* __restrict__ nodef,
                    const int* __restrict__ eidx,
                    const float* __restrict__ eattr,
                    const float* __restrict__ W1, const float* __restrict__ b1,
                    const float* __restrict__ g1, const float* __restrict__ be1,
                    const float* __restrict__ W2, const float* __restrict__ b2,
                    const float* __restrict__ g2, const float* __restrict__ be2,
                    const float* __restrict__ W3, const float* __restrict__ b3,
                    float* __restrict__ out, int E)
{
    extern __shared__ float sm[];
    const int tid = threadIdx.x;

    // ---- stage weights, permuted k-layout: within each 16-k chunk,
    // position p = tg*4 + j holds original k = chunk*16 + j*4 + tg ----
    for (int i = tid; i < 64 * 144; i += NTHREADS) {
        const int n = i / 144, p = i % 144;
        const int c = p >> 4, q = p & 15, tg_s = q >> 2, j = q & 3;
        const int k = c * 16 + j * 4 + tg_s;
        sm[oW1 + n * WS1 + p] = tf32r(W1[k * 64 + n]);
    }
    for (int i = tid; i < 64 * 64; i += NTHREADS) {
        const int n = i >> 6, p = i & 63;
        const int c = p >> 4, q = p & 15, tg_s = q >> 2, j = q & 3;
        const int k = c * 16 + j * 4 + tg_s;
        sm[oW2 + n * WS2 + p] = tf32r(W2[k * 64 + n]);
    }
    if (tid < 64) {
        sm[oP + tid]        = b1[tid];
        sm[oP + 64  + tid]  = g1[tid];
        sm[oP + 128 + tid]  = be1[tid];
        sm[oP + 192 + tid]  = b2[tid];
        sm[oP + 256 + tid]  = g2[tid];
        sm[oP + 320 + tid]  = be2[tid];
        sm[oP + 384 + tid]  = W3[tid];
    }
    if (tid == 0) sm[oP + 448] = b3[0];
    __syncthreads();

    const int warp = tid >> 5, lane = tid & 31;
    const int g = lane >> 2, tg = lane & 3;
    float* const Aw = &sm[oA + warp * 32 * ASL];   // warp-private 32-row slice

    const int nChunks = (E + 31) / 32;

    for (int ch = blockIdx.x * NW + warp; ch < nChunks; ch += gridDim.x * NW) {
        const int base = ch * 32;
        const int e = base + lane;

        // per-lane edge indices (coalesced), broadcast later via shfl
        int si = 0, di = 0;
        if (e < E) {
            si = eidx[e];
            di = eidx[(size_t)E + e];
        }

        __syncwarp();   // prior iteration's H reads done before overwrite

        // ---------------- phase A: gather src features (k 0..63), coalesced ----------------
        gather_nodes(Aw, nodef, si, base, E, lane);
        __syncwarp();

        float acc[2][8][4];
        #pragma unroll
        for (int mt = 0; mt < 2; mt++)
            #pragma unroll
            for (int nf = 0; nf < 8; nf++)
                acc[mt][nf][0] = acc[mt][nf][1] = acc[mt][nf][2] = acc[mt][nf][3] = 0.f;

        // GEMM1 phase A: buffer chunks 0..3 <-> W1 chunks 0..3 (k 0..63)
        gemm_phase(acc, Aw, &sm[oW1 + g * WS1 + tg * 4], 4, 0, WS1, g, tg);
        __syncwarp();   // phase-A reads done before overwrite

        // ---------------- phase B: gather dst (k->0..63) + eattr (k->64..79), coalesced ----------------
        gather_nodes(Aw, nodef, di, base, E, lane);
        {
            // eattr: 4 lanes per row (16 floats), 8 rows per iteration, contiguous
            const int rsub = lane >> 2;       // 0..7
            const int fi = lane & 3;          // float4 index within 16-float attr
            #pragma unroll
            for (int it = 0; it < 4; it++) {
                const int row = it * 8 + rsub;
                float4 v = make_float4(0.f, 0.f, 0.f, 0.f);
                if (base + row < E) {
                    v = *reinterpret_cast<const float4*>(eattr + (size_t)(base + row) * 16 + fi * 4);
                    v.x = tf32r(v.x); v.y = tf32r(v.y); v.z = tf32r(v.z); v.w = tf32r(v.w);
                }
                *reinterpret_cast<float4*>(Aw + row * ASL + 64 + fi * 4) = v;
            }
        }
        __syncwarp();

        // GEMM1 phase B: buffer chunks 0..4 <-> W1 chunks 4..8 (k 64..143)
        gemm_phase(acc, Aw, &sm[oW1 + g * WS1 + tg * 4], 5, 4, WS1, g, tg);
        __syncwarp();   // phase-B reads done before H overwrite

        // ---------------- bias + LN1 + LeakyReLU -> H (tf32, buffer k 0..63) ----------------
        {
            float s[4] = {0.f, 0.f, 0.f, 0.f}, q[4] = {0.f, 0.f, 0.f, 0.f};
            #pragma unroll
            for (int mt = 0; mt < 2; mt++)
                #pragma unroll
                for (int nf = 0; nf < 8; nf++) {
                    const int col = nf * 8 + tg * 2;
                    const float bc0 = sm[oP + col], bc1 = sm[oP + col + 1];
                    float* a = acc[mt][nf];
                    a[0] += bc0; a[1] += bc1; a[2] += bc0; a[3] += bc1;
                    s[mt * 2]     += a[0] + a[1];
                    q[mt * 2]     += a[0] * a[0] + a[1] * a[1];
                    s[mt * 2 + 1] += a[2] + a[3];
                    q[mt * 2 + 1] += a[2] * a[2] + a[3] * a[3];
                }
            float mu[4], is[4];
            #pragma unroll
            for (int r = 0; r < 4; r++) {
                s[r] += __shfl_xor_sync(0xffffffffu, s[r], 1);
                s[r] += __shfl_xor_sync(0xffffffffu, s[r], 2);
                q[r] += __shfl_xor_sync(0xffffffffu, q[r], 1);
                q[r] += __shfl_xor_sync(0xffffffffu, q[r], 2);
                mu[r] = s[r] * (1.f / HID);
                is[r] = rsqrtf(fmaxf(q[r] * (1.f / HID) - mu[r] * mu[r], 0.f) + 1e-5f);
            }
            #pragma unroll
            for (int mt = 0; mt < 2; mt++) {
                float* h0p = Aw + (g + mt * 16) * ASL;
                float* h1p = Aw + (g + 8 + mt * 16) * ASL;
                const float mu0 = mu[mt * 2], is0 = is[mt * 2];
                const float mu1 = mu[mt * 2 + 1], is1 = is[mt * 2 + 1];
                #pragma unroll
                for (int nf = 0; nf < 8; nf++) {
                    const int col = nf * 8 + tg * 2;
                    const float ga0 = sm[oP + 64 + col],  ga1 = sm[oP + 64 + col + 1];
                    const float bb0 = sm[oP + 128 + col], bb1 = sm[oP + 128 + col + 1];
                    const float* a = acc[mt][nf];
                    float h00 = (a[0] - mu0) * is0 * ga0 + bb0;
                    float h01 = (a[1] - mu0) * is0 * ga1 + bb1;
                    float h10 = (a[2] - mu1) * is1 * ga0 + bb0;
                    float h11 = (a[3] - mu1) * is1 * ga1 + bb1;
                    h00 = h00 < 0.f ? 0.1f * h00 : h00;
                    h01 = h01 < 0.f ? 0.1f * h01 : h01;
                    h10 = h10 < 0.f ? 0.1f * h10 : h10;
                    h11 = h11 < 0.f ? 0.1f * h11 : h11;
                    *reinterpret_cast<float2*>(h0p + col) = make_float2(tf32r(h00), tf32r(h01));
                    *reinterpret_cast<float2*>(h1p + col) = make_float2(tf32r(h10), tf32r(h11));
                }
            }
        }
        __syncwarp();

        // ---------------- GEMM2: 32 rows x 64 x K=64 ----------------
        #pragma unroll
        for (int mt = 0; mt < 2; mt++)
            #pragma unroll
            for (int nf = 0; nf < 8; nf++)
                acc[mt][nf][0] = acc[mt][nf][1] = acc[mt][nf][2] = acc[mt][nf][3] = 0.f;
        gemm_phase(acc, Aw, &sm[oW2 + g * WS2 + tg * 4], 4, 0, WS2, g, tg);

        // ---------------- bias + LN2 + LeakyReLU + layer3 dot -> out ----------------
        {
            float s[4] = {0.f, 0.f, 0.f, 0.f}, q[4] = {0.f, 0.f, 0.f, 0.f};
            #pragma unroll
            for (int mt = 0; mt < 2; mt++)
                #pragma unroll
                for (int nf = 0; nf < 8; nf++) {
                    const int col = nf * 8 + tg * 2;
                    const float bc0 = sm[oP + 192 + col], bc1 = sm[oP + 192 + col + 1];
                    float* a = acc[mt][nf];
                    a[0] += bc0; a[1] += bc1; a[2] += bc0; a[3] += bc1;
                    s[mt * 2]     += a[0] + a[1];
                    q[mt * 2]     += a[0] * a[0] + a[1] * a[1];
                    s[mt * 2 + 1] += a[2] + a[3];
                    q[mt * 2 + 1] += a[2] * a[2] + a[3] * a[3];
                }
            float mu[4], is[4];
            #pragma unroll
            for (int r = 0; r < 4; r++) {
                s[r] += __shfl_xor_sync(0xffffffffu, s[r], 1);
                s[r] += __shfl_xor_sync(0xffffffffu, s[r], 2);
                q[r] += __shfl_xor_sync(0xffffffffu, q[r], 1);
                q[r] += __shfl_xor_sync(0xffffffffu, q[r], 2);
                mu[r] = s[r] * (1.f / HID);
                is[r] = rsqrtf(fmaxf(q[r] * (1.f / HID) - mu[r] * mu[r], 0.f) + 1e-5f);
            }
            float y[4] = {0.f, 0.f, 0.f, 0.f};
            #pragma unroll
            for (int mt = 0; mt < 2; mt++)
                #pragma unroll
                for (int nf = 0; nf < 8; nf++) {
                    const int col = nf * 8 + tg * 2;
                    const float ga0 = sm[oP + 256 + col], ga1 = sm[oP + 256 + col + 1];
                    const float bb0 = sm[oP + 320 + col], bb1 = sm[oP + 320 + col + 1];
                    const float w30 = sm[oP + 384 + col], w31 = sm[oP + 384 + col + 1];
                    const float* a = acc[mt][nf];
                    float h00 = (a[0] - mu[mt * 2]) * is[mt * 2] * ga0 + bb0;
                    float h01 = (a[1] - mu[mt * 2]) * is[mt * 2] * ga1 + bb1;
                    float h10 = (a[2] - mu[mt * 2 + 1]) * is[mt * 2 + 1] * ga0 + bb0;
                    float h11 = (a[3] - mu[mt * 2 + 1]) * is[mt * 2 + 1] * ga1 + bb1;
                    h00 = h00 < 0.f ? 0.1f * h00 : h00;
                    h01 = h01 < 0.f ? 0.1f * h01 : h01;
                    h10 = h10 < 0.f ? 0.1f * h10 : h10;
                    h11 = h11 < 0.f ? 0.1f * h11 : h11;
                    y[mt * 2]     += h00 * w30 + h01 * w31;
                    y[mt * 2 + 1] += h10 * w30 + h11 * w31;
                }
            #pragma unroll
            for (int r = 0; r < 4; r++) {
                y[r] += __shfl_xor_sync(0xffffffffu, y[r], 1);
                y[r] += __shfl_xor_sync(0xffffffffu, y[r], 2);
            }
            if (tg == 0) {
                const float b3s = sm[oP + 448];
                #pragma unroll
                for (int r = 0; r < 4; r++) {
                    const int eo = base + g + ((r & 1) ? 8 : 0) + ((r >> 1) ? 16 : 0);
                    if (eo < E) out[eo] = y[r] + b3s;
                }
            }
        }
    }
}

extern "C" void kernel_launch(void* const* d_in, const int* in_sizes, int n_in,
                              void* d_out, int out_size) {
    const float* nodef = (const float*)d_in[0];
    const int*   eidx  = (const int*)d_in[1];
    const float* eattr = (const float*)d_in[2];
    const float* W1 = (const float*)d_in[3];
    const float* b1 = (const float*)d_in[4];
    const float* g1 = (const float*)d_in[5];
    const float* be1 = (const float*)d_in[6];
    const float* W2 = (const float*)d_in[7];
    const float* b2 = (const float*)d_in[8];
    const float* g2 = (const float*)d_in[9];
    const float* be2 = (const float*)d_in[10];
    const float* W3 = (const float*)d_in[11];
    const float* b3 = (const float*)d_in[12];
    float* out = (float*)d_out;

    const int E = out_size;
    if (E <= 0) return;

    cudaFuncSetAttribute(edgenet_kernel, cudaFuncAttributeMaxDynamicSharedMemorySize, SMEM_BYTES);

    int dev = 0;
    cudaGetDevice(&dev);
    int sms = 148;
    cudaDeviceGetAttribute(&sms, cudaDevAttrMultiProcessorCount, dev);

    const int nChunks = (E + 31) / 32;
    const int ctasNeeded = (nChunks + NW - 1) / NW;
    const int grid = (ctasNeeded < sms) ? ctasNeeded : sms;

    edgenet_kernel<<<grid, NTHREADS, SMEM_BYTES>>>(
        nodef, eidx, eattr, W1, b1, g1, be1, W2, b2, g2, be2, W3, b3, out, E);
}

// round 8
// speedup vs baseline: 1.3968x; 1.2291x over previous
#include <cuda_runtime.h>
#include <cstdint>
#include <cstddef>

#define HID      64
#define NTHREADS 384
#define NW       12     // warps per CTA

#define ASL  84    // A/H slice row stride (floats): banks within each frag-load instr all distinct
#define WS1  144   // W1T row stride: ≡ 16 (mod 32) -> conflict-free LDS.128 (per-8-lane phases)
#define WS2  80    // W2T row stride: ≡ 16 (mod 32)

// SMEM layout (float offsets)
#define oW1 0                        // W1 permuted  [64][WS1]
#define oW2 (oW1 + 64*WS1)           // W2 permuted  [64][WS2]
#define oA  (oW2 + 64*WS2)           // per-warp slices: NW x 32 x ASL  (src->dst+eattr->H reuse)
#define oP  (oA + NW*32*ASL)         // b1,g1,be1,b2,g2,be2,W3 (7x64) + b3
#define SMEM_FLOATS (oP + 452)
#define SMEM_BYTES  (SMEM_FLOATS * 4)   // 188,176 B

// pre-rounded node-feature table (tf32 values stored as f32). 64 MB static scratch.
#define MAX_NODE_FLOATS (16 * 1024 * 1024)
__device__ __align__(16) float g_nodes[MAX_NODE_FLOATS];

__device__ __forceinline__ float tf32r(float x) {
    unsigned u;
    asm("cvt.rna.tf32.f32 %0, %1;" : "=r"(u) : "f"(x));
    return __uint_as_float(u);
}

__device__ __forceinline__ void mma_tf32(float* c,
                                         unsigned a0, unsigned a1, unsigned a2, unsigned a3,
                                         unsigned b0, unsigned b1) {
    asm volatile(
        "mma.sync.aligned.m16n8k8.row.col.f32.tf32.tf32.f32 "
        "{%0,%1,%2,%3}, {%4,%5,%6,%7}, {%8,%9}, {%0,%1,%2,%3};"
        : "+f"(c[0]), "+f"(c[1]), "+f"(c[2]), "+f"(c[3])
        : "r"(a0), "r"(a1), "r"(a2), "r"(a3), "r"(b0), "r"(b1));
}

// prologue: round the node table once (grid-stride, vectorized)
__global__ void round_nodes_kernel(const float4* __restrict__ src, int n4) {
    for (int i = blockIdx.x * blockDim.x + threadIdx.x; i < n4; i += gridDim.x * blockDim.x) {
        float4 v = src[i];
        v.x = tf32r(v.x); v.y = tf32r(v.y); v.z = tf32r(v.z); v.w = tf32r(v.w);
        reinterpret_cast<float4*>(g_nodes)[i] = v;
    }
}

// one K-chunk-range of GEMM accumulation: buffer chunks [0, nc), weight chunks [wc0, wc0+nc)
__device__ __forceinline__ void gemm_phase(float acc[2][8][4],
                                           const float* __restrict__ Aw,
                                           const float* __restrict__ Bw,
                                           int nc, int wc0, int ws,
                                           int g, int tg) {
    #pragma unroll
    for (int c = 0; c < nc; c++) {
        const int kc = c * 16;
        const int kw = (wc0 + c) * 16;
        float4 bv[8];
        #pragma unroll
        for (int nf = 0; nf < 8; nf++)
            bv[nf] = *reinterpret_cast<const float4*>(Bw + nf * 8 * ws + kw);
        #pragma unroll
        for (int s = 0; s < 2; s++) {
            const int k = kc + s * 8 + tg;
            unsigned a00 = __float_as_uint(Aw[g * ASL + k]);
            unsigned a01 = __float_as_uint(Aw[(g + 8) * ASL + k]);
            unsigned a02 = __float_as_uint(Aw[g * ASL + k + 4]);
            unsigned a03 = __float_as_uint(Aw[(g + 8) * ASL + k + 4]);
            unsigned a10 = __float_as_uint(Aw[(g + 16) * ASL + k]);
            unsigned a11 = __float_as_uint(Aw[(g + 24) * ASL + k]);
            unsigned a12 = __float_as_uint(Aw[(g + 16) * ASL + k + 4]);
            unsigned a13 = __float_as_uint(Aw[(g + 24) * ASL + k + 4]);
            #pragma unroll
            for (int nf = 0; nf < 8; nf++) {
                const unsigned bb0 = s ? __float_as_uint(bv[nf].z) : __float_as_uint(bv[nf].x);
                const unsigned bb1 = s ? __float_as_uint(bv[nf].w) : __float_as_uint(bv[nf].y);
                mma_tf32(acc[0][nf], a00, a01, a02, a03, bb0, bb1);
                mma_tf32(acc[1][nf], a10, a11, a12, a13, bb0, bb1);
            }
        }
    }
}

// cooperative coalesced gather of 32 node rows into the warp slice:
// 16 lanes per row (one float4 each), 2 rows per iteration, index via shfl.
// PRE: rows come from the pre-rounded g_nodes table (no cvt); else round inline.
template <bool PRE>
__device__ __forceinline__ void gather_nodes(float* __restrict__ Aw,
                                             const float* __restrict__ nsrc,
                                             int idx_lane, int base, int E, int lane) {
    const int half = lane >> 4;        // 0/1: which of the 2 rows this iteration
    const int fi = lane & 15;          // float4 index within the 64-float row
    #pragma unroll
    for (int it = 0; it < 16; it++) {
        const int row = it * 2 + half;
        const int nrow = __shfl_sync(0xffffffffu, idx_lane, row);
        float4 v = make_float4(0.f, 0.f, 0.f, 0.f);
        if (base + row < E) {
            v = *reinterpret_cast<const float4*>(nsrc + (size_t)nrow * 64 + fi * 4);
            if (!PRE) { v.x = tf32r(v.x); v.y = tf32r(v.y); v.z = tf32r(v.z); v.w = tf32r(v.w); }
        }
        *reinterpret_cast<float4*>(Aw + row * ASL + fi * 4) = v;
    }
}

template <bool PRE>
__global__ __launch_bounds__(NTHREADS, 1)
void edgenet_kernel(const float* __restrict__ nodef,
                    const int* __restrict__ eidx,
                    const float* __restrict__ eattr,
                    const float* __restrict__ W1, const float* __restrict__ b1,
                    const float* __restrict__ g1, const float* __restrict__ be1,
                    const float* __restrict__ W2, const float* __restrict__ b2,
                    const float* __restrict__ g2, const float* __restrict__ be2,
                    const float* __restrict__ W3, const float* __restrict__ b3,
                    float* __restrict__ out, int E)
{
    extern __shared__ float sm[];
    const int tid = threadIdx.x;

    // ---- stage weights, permuted k-layout: within each 16-k chunk,
    // position p = tg*4 + j holds original k = chunk*16 + j*4 + tg ----
    for (int i = tid; i < 64 * 144; i += NTHREADS) {
        const int n = i / 144, p = i % 144;
        const int c = p >> 4, q = p & 15, tg_s = q >> 2, j = q & 3;
        const int k = c * 16 + j * 4 + tg_s;
        sm[oW1 + n * WS1 + p] = tf32r(W1[k * 64 + n]);
    }
    for (int i = tid; i < 64 * 64; i += NTHREADS) {
        const int n = i >> 6, p = i & 63;
        const int c = p >> 4, q = p & 15, tg_s = q >> 2, j = q & 3;
        const int k = c * 16 + j * 4 + tg_s;
        sm[oW2 + n * WS2 + p] = tf32r(W2[k * 64 + n]);
    }
    if (tid < 64) {
        sm[oP + tid]        = b1[tid];
        sm[oP + 64  + tid]  = g1[tid];
        sm[oP + 128 + tid]  = be1[tid];
        sm[oP + 192 + tid]  = b2[tid];
        sm[oP + 256 + tid]  = g2[tid];
        sm[oP + 320 + tid]  = be2[tid];
        sm[oP + 384 + tid]  = W3[tid];
    }
    if (tid == 0) sm[oP + 448] = b3[0];
    __syncthreads();

    const int warp = tid >> 5, lane = tid & 31;
    const int g = lane >> 2, tg = lane & 3;
    float* const Aw = &sm[oA + warp * 32 * ASL];   // warp-private 32-row slice
    const float* const nsrc = PRE ? g_nodes : nodef;

    const int nChunks = (E + 31) / 32;

    for (int ch = blockIdx.x * NW + warp; ch < nChunks; ch += gridDim.x * NW) {
        const int base = ch * 32;
        const int e = base + lane;

        // per-lane edge indices (coalesced), broadcast later via shfl
        int si = 0, di = 0;
        if (e < E) {
            si = eidx[e];
            di = eidx[(size_t)E + e];
        }

        __syncwarp();   // prior iteration's H reads done before overwrite

        // ---------------- phase A: gather src features (k 0..63), coalesced ----------------
        gather_nodes<PRE>(Aw, nsrc, si, base, E, lane);
        __syncwarp();

        float acc[2][8][4];
        #pragma unroll
        for (int mt = 0; mt < 2; mt++)
            #pragma unroll
            for (int nf = 0; nf < 8; nf++)
                acc[mt][nf][0] = acc[mt][nf][1] = acc[mt][nf][2] = acc[mt][nf][3] = 0.f;

        // GEMM1 phase A: buffer chunks 0..3 <-> W1 chunks 0..3 (k 0..63)
        gemm_phase(acc, Aw, &sm[oW1 + g * WS1 + tg * 4], 4, 0, WS1, g, tg);
        __syncwarp();   // phase-A reads done before overwrite

        // ---------------- phase B: gather dst (k->0..63) + eattr (k->64..79), coalesced ----------------
        gather_nodes<PRE>(Aw, nsrc, di, base, E, lane);
        {
            // eattr: 4 lanes per row (16 floats), 8 rows per iteration, contiguous
            const int rsub = lane >> 2;       // 0..7
            const int fi = lane & 3;          // float4 index within 16-float attr
            #pragma unroll
            for (int it = 0; it < 4; it++) {
                const int row = it * 8 + rsub;
                float4 v = make_float4(0.f, 0.f, 0.f, 0.f);
                if (base + row < E) {
                    v = *reinterpret_cast<const float4*>(eattr + (size_t)(base + row) * 16 + fi * 4);
                    v.x = tf32r(v.x); v.y = tf32r(v.y); v.z = tf32r(v.z); v.w = tf32r(v.w);
                }
                *reinterpret_cast<float4*>(Aw + row * ASL + 64 + fi * 4) = v;
            }
        }
        __syncwarp();

        // GEMM1 phase B: buffer chunks 0..4 <-> W1 chunks 4..8 (k 64..143)
        gemm_phase(acc, Aw, &sm[oW1 + g * WS1 + tg * 4], 5, 4, WS1, g, tg);
        __syncwarp();   // phase-B reads done before H overwrite

        // ---------------- bias + LN1 + LeakyReLU -> H (tf32, buffer k 0..63) ----------------
        {
            float s[4] = {0.f, 0.f, 0.f, 0.f}, q[4] = {0.f, 0.f, 0.f, 0.f};
            #pragma unroll
            for (int mt = 0; mt < 2; mt++)
                #pragma unroll
                for (int nf = 0; nf < 8; nf++) {
                    const int col = nf * 8 + tg * 2;
                    const float bc0 = sm[oP + col], bc1 = sm[oP + col + 1];
                    float* a = acc[mt][nf];
                    a[0] += bc0; a[1] += bc1; a[2] += bc0; a[3] += bc1;
                    s[mt * 2]     += a[0] + a[1];
                    q[mt * 2]     += a[0] * a[0] + a[1] * a[1];
                    s[mt * 2 + 1] += a[2] + a[3];
                    q[mt * 2 + 1] += a[2] * a[2] + a[3] * a[3];
                }
            float mu[4], is[4];
            #pragma unroll
            for (int r = 0; r < 4; r++) {
                s[r] += __shfl_xor_sync(0xffffffffu, s[r], 1);
                s[r] += __shfl_xor_sync(0xffffffffu, s[r], 2);
                q[r] += __shfl_xor_sync(0xffffffffu, q[r], 1);
                q[r] += __shfl_xor_sync(0xffffffffu, q[r], 2);
                mu[r] = s[r] * (1.f / HID);
                is[r] = rsqrtf(fmaxf(q[r] * (1.f / HID) - mu[r] * mu[r], 0.f) + 1e-5f);
            }
            #pragma unroll
            for (int mt = 0; mt < 2; mt++) {
                float* h0p = Aw + (g + mt * 16) * ASL;
                float* h1p = Aw + (g + 8 + mt * 16) * ASL;
                const float mu0 = mu[mt * 2], is0 = is[mt * 2];
                const float mu1 = mu[mt * 2 + 1], is1 = is[mt * 2 + 1];
                #pragma unroll
                for (int nf = 0; nf < 8; nf++) {
                    const int col = nf * 8 + tg * 2;
                    const float ga0 = sm[oP + 64 + col],  ga1 = sm[oP + 64 + col + 1];
                    const float bb0 = sm[oP + 128 + col], bb1 = sm[oP + 128 + col + 1];
                    const float* a = acc[mt][nf];
                    float h00 = (a[0] - mu0) * is0 * ga0 + bb0;
                    float h01 = (a[1] - mu0) * is0 * ga1 + bb1;
                    float h10 = (a[2] - mu1) * is1 * ga0 + bb0;
                    float h11 = (a[3] - mu1) * is1 * ga1 + bb1;
                    h00 = h00 < 0.f ? 0.1f * h00 : h00;
                    h01 = h01 < 0.f ? 0.1f * h01 : h01;
                    h10 = h10 < 0.f ? 0.1f * h10 : h10;
                    h11 = h11 < 0.f ? 0.1f * h11 : h11;
                    *reinterpret_cast<float2*>(h0p + col) = make_float2(tf32r(h00), tf32r(h01));
                    *reinterpret_cast<float2*>(h1p + col) = make_float2(tf32r(h10), tf32r(h11));
                }
            }
        }
        __syncwarp();

        // ---------------- GEMM2: 32 rows x 64 x K=64 ----------------
        #pragma unroll
        for (int mt = 0; mt < 2; mt++)
            #pragma unroll
            for (int nf = 0; nf < 8; nf++)
                acc[mt][nf][0] = acc[mt][nf][1] = acc[mt][nf][2] = acc[mt][nf][3] = 0.f;
        gemm_phase(acc, Aw, &sm[oW2 + g * WS2 + tg * 4], 4, 0, WS2, g, tg);

        // ---------------- bias + LN2 + LeakyReLU + layer3 dot -> out ----------------
        {
            float s[4] = {0.f, 0.f, 0.f, 0.f}, q[4] = {0.f, 0.f, 0.f, 0.f};
            #pragma unroll
            for (int mt = 0; mt < 2; mt++)
                #pragma unroll
                for (int nf = 0; nf < 8; nf++) {
                    const int col = nf * 8 + tg * 2;
                    const float bc0 = sm[oP + 192 + col], bc1 = sm[oP + 192 + col + 1];
                    float* a = acc[mt][nf];
                    a[0] += bc0; a[1] += bc1; a[2] += bc0; a[3] += bc1;
                    s[mt * 2]     += a[0] + a[1];
                    q[mt * 2]     += a[0] * a[0] + a[1] * a[1];
                    s[mt * 2 + 1] += a[2] + a[3];
                    q[mt * 2 + 1] += a[2] * a[2] + a[3] * a[3];
                }
            float mu[4], is[4];
            #pragma unroll
            for (int r = 0; r < 4; r++) {
                s[r] += __shfl_xor_sync(0xffffffffu, s[r], 1);
                s[r] += __shfl_xor_sync(0xffffffffu, s[r], 2);
                q[r] += __shfl_xor_sync(0xffffffffu, q[r], 1);
                q[r] += __shfl_xor_sync(0xffffffffu, q[r], 2);
                mu[r] = s[r] * (1.f / HID);
                is[r] = rsqrtf(fmaxf(q[r] * (1.f / HID) - mu[r] * mu[r], 0.f) + 1e-5f);
            }
            float y[4] = {0.f, 0.f, 0.f, 0.f};
            #pragma unroll
            for (int mt = 0; mt < 2; mt++)
                #pragma unroll
                for (int nf = 0; nf < 8; nf++) {
                    const int col = nf * 8 + tg * 2;
                    const float ga0 = sm[oP + 256 + col], ga1 = sm[oP + 256 + col + 1];
                    const float bb0 = sm[oP + 320 + col], bb1 = sm[oP + 320 + col + 1];
                    const float w30 = sm[oP + 384 + col], w31 = sm[oP + 384 + col + 1];
                    const float* a = acc[mt][nf];
                    float h00 = (a[0] - mu[mt * 2]) * is[mt * 2] * ga0 + bb0;
                    float h01 = (a[1] - mu[mt * 2]) * is[mt * 2] * ga1 + bb1;
                    float h10 = (a[2] - mu[mt * 2 + 1]) * is[mt * 2 + 1] * ga0 + bb0;
                    float h11 = (a[3] - mu[mt * 2 + 1]) * is[mt * 2 + 1] * ga1 + bb1;
                    h00 = h00 < 0.f ? 0.1f * h00 : h00;
                    h01 = h01 < 0.f ? 0.1f * h01 : h01;
                    h10 = h10 < 0.f ? 0.1f * h10 : h10;
                    h11 = h11 < 0.f ? 0.1f * h11 : h11;
                    y[mt * 2]     += h00 * w30 + h01 * w31;
                    y[mt * 2 + 1] += h10 * w30 + h11 * w31;
                }
            #pragma unroll
            for (int r = 0; r < 4; r++) {
                y[r] += __shfl_xor_sync(0xffffffffu, y[r], 1);
                y[r] += __shfl_xor_sync(0xffffffffu, y[r], 2);
            }
            if (tg == 0) {
                const float b3s = sm[oP + 448];
                #pragma unroll
                for (int r = 0; r < 4; r++) {
                    const int eo = base + g + ((r & 1) ? 8 : 0) + ((r >> 1) ? 16 : 0);
                    if (eo < E) out[eo] = y[r] + b3s;
                }
            }
        }
    }
}

extern "C" void kernel_launch(void* const* d_in, const int* in_sizes, int n_in,
                              void* d_out, int out_size) {
    const float* nodef = (const float*)d_in[0];
    const int*   eidx  = (const int*)d_in[1];
    const float* eattr = (const float*)d_in[2];
    const float* W1 = (const float*)d_in[3];
    const float* b1 = (const float*)d_in[4];
    const float* g1 = (const float*)d_in[5];
    const float* be1 = (const float*)d_in[6];
    const float* W2 = (const float*)d_in[7];
    const float* b2 = (const float*)d_in[8];
    const float* g2 = (const float*)d_in[9];
    const float* be2 = (const float*)d_in[10];
    const float* W3 = (const float*)d_in[11];
    const float* b3 = (const float*)d_in[12];
    float* out = (float*)d_out;

    const int E = out_size;
    if (E <= 0) return;

    int dev = 0;
    cudaGetDevice(&dev);
    int sms = 148;
    cudaDeviceGetAttribute(&sms, cudaDevAttrMultiProcessorCount, dev);

    const int nChunks = (E + 31) / 32;
    const int ctasNeeded = (nChunks + NW - 1) / NW;
    const int grid = (ctasNeeded < sms) ? ctasNeeded : sms;

    const int nodeElems = in_sizes[0];          // n_nodes * 64
    const bool pre = (nodeElems > 0) && (nodeElems <= MAX_NODE_FLOATS) && ((nodeElems & 3) == 0);

    if (pre) {
        const int n4 = nodeElems >> 2;
        int pgrid = (n4 + 255) / 256;
        if (pgrid > 2 * sms) pgrid = 2 * sms;
        round_nodes_kernel<<<pgrid, 256>>>(reinterpret_cast<const float4*>(nodef), n4);

        cudaFuncSetAttribute(edgenet_kernel<true>, cudaFuncAttributeMaxDynamicSharedMemorySize, SMEM_BYTES);
        edgenet_kernel<true><<<grid, NTHREADS, SMEM_BYTES>>>(
            nodef, eidx, eattr, W1, b1, g1, be1, W2, b2, g2, be2, W3, b3, out, E);
    } else {
        cudaFuncSetAttribute(edgenet_kernel<false>, cudaFuncAttributeMaxDynamicSharedMemorySize, SMEM_BYTES);
        edgenet_kernel<false><<<grid, NTHREADS, SMEM_BYTES>>>(
            nodef, eidx, eattr, W1, b1, g1, be1, W2, b2, g2, be2, W3, b3, out, E);
    }
}

// round 9
// speedup vs baseline: 1.8860x; 1.3502x over previous
#include <cuda_runtime.h>
#include <cuda_fp16.h>
#include <cstdint>
#include <cstddef>

#define HID      64
#define NTHREADS 384
#define NW       12     // warps per CTA

// byte strides (rows of fp16 data)
#define RSA  288   // A slice & W1 row stride: 72 words ≡ 8 (mod 32) -> conflict-free LDS.64
#define RSW2 160   // W2 row stride: 40 words ≡ 8 (mod 32) -> conflict-free LDS.64

// SMEM byte layout
#define oW1 0                        // W1 permuted fp16 [64][144h = 288B]
#define oW2 (oW1 + 64*RSA)           // W2 permuted fp16 [64][80h = 160B]
#define oA  (oW2 + 64*RSW2)          // per-warp slices: NW x 32 rows x 288B (src->dst+eattr->H)
#define oP  (oA + NW*32*RSA)         // f32 params: b1,g1,be1,b2,g2,be2,W3 (7x64) + b3
#define SMEM_BYTES (oP + 452*4)

// pre-converted fp16 node-feature table (32 MB static scratch)
#define MAX_NODE_ELEMS (16 * 1024 * 1024)
__device__ __align__(16) __half g_nodes[MAX_NODE_ELEMS];

__device__ __forceinline__ unsigned packh2(float a, float b) {
    __half2 h = __floats2half2_rn(a, b);
    return *reinterpret_cast<unsigned*>(&h);
}

__device__ __forceinline__ void mma_f16(float* c,
                                        unsigned a0, unsigned a1, unsigned a2, unsigned a3,
                                        unsigned b0, unsigned b1) {
    asm volatile(
        "mma.sync.aligned.m16n8k16.row.col.f32.f16.f16.f32 "
        "{%0,%1,%2,%3}, {%4,%5,%6,%7}, {%8,%9}, {%0,%1,%2,%3};"
        : "+f"(c[0]), "+f"(c[1]), "+f"(c[2]), "+f"(c[3])
        : "r"(a0), "r"(a1), "r"(a2), "r"(a3), "r"(b0), "r"(b1));
}

// prologue: convert node table f32 -> fp16 once (grid-stride, vectorized)
__global__ void conv_nodes_kernel(const float4* __restrict__ src, int n4) {
    for (int i = blockIdx.x * blockDim.x + threadIdx.x; i < n4; i += gridDim.x * blockDim.x) {
        float4 v = src[i];
        uint2 o;
        o.x = packh2(v.x, v.y);
        o.y = packh2(v.z, v.w);
        reinterpret_cast<uint2*>(g_nodes)[i] = o;
    }
}

// permuted position within a 16-k chunk: pair (2tg,2tg+1)->bytes tg*8; (2tg+8,2tg+9)->tg*8+4
// for a source float4 index m = fi&3 (k%16 = 4m..4m+3): first pair byte base:
__device__ __forceinline__ int pair_base(int m) { return ((m & 1) * 16) + ((m >> 1) * 4); }

// one K-range of fp16 GEMM accumulation: buffer chunks [0,nc) vs weight chunks [wc0,wc0+nc)
template <int NC>
__device__ __forceinline__ void gemm_f16(float acc[2][8][4],
                                         const char* __restrict__ Ab,   // + g*RSA + tg*8
                                         const char* __restrict__ Bb,   // + g*ws + tg*8
                                         int wc0, int ws) {
    #pragma unroll
    for (int c = 0; c < NC; c++) {
        uint2 bv[8];
        #pragma unroll
        for (int nf = 0; nf < 8; nf++)
            bv[nf] = *reinterpret_cast<const uint2*>(Bb + nf * 8 * ws + (wc0 + c) * 32);
        #pragma unroll
        for (int mt = 0; mt < 2; mt++) {
            const uint2 r0 = *reinterpret_cast<const uint2*>(Ab + (mt * 16) * RSA + c * 32);
            const uint2 r1 = *reinterpret_cast<const uint2*>(Ab + (8 + mt * 16) * RSA + c * 32);
            #pragma unroll
            for (int nf = 0; nf < 8; nf++)
                mma_f16(acc[mt][nf], r0.x, r1.x, r0.y, r1.y, bv[nf].x, bv[nf].y);
        }
    }
}

// cooperative coalesced gather of 32 node rows (fp16) into the warp slice.
// 16 lanes per row (8 bytes = 4 halfs each), 2 rows per iteration, index via shfl.
template <bool PRE>
__device__ __forceinline__ void gather_nodes(char* __restrict__ Aw,
                                             const float* __restrict__ nodef,
                                             int idx_lane, int base, int E, int lane) {
    const int half_ = lane >> 4;
    const int fi = lane & 15;
    const int c = fi >> 2, m = fi & 3;
    const int off1 = c * 32 + pair_base(m);
    #pragma unroll
    for (int it = 0; it < 16; it++) {
        const int row = it * 2 + half_;
        const int nrow = __shfl_sync(0xffffffffu, idx_lane, row);
        uint2 o = make_uint2(0u, 0u);
        if (base + row < E) {
            if (PRE) {
                o = *reinterpret_cast<const uint2*>(
                        reinterpret_cast<const char*>(g_nodes) + (size_t)nrow * 128 + fi * 8);
            } else {
                float4 v = *reinterpret_cast<const float4*>(nodef + (size_t)nrow * 64 + fi * 4);
                o.x = packh2(v.x, v.y);
                o.y = packh2(v.z, v.w);
            }
        }
        char* rp = Aw + row * RSA;
        *reinterpret_cast<unsigned*>(rp + off1)     = o.x;
        *reinterpret_cast<unsigned*>(rp + off1 + 8) = o.y;
    }
}

template <bool PRE>
__global__ __launch_bounds__(NTHREADS, 1)
void edgenet_kernel(const float* __restrict__ nodef,
                    const int* __restrict__ eidx,
                    const float* __restrict__ eattr,
                    const float* __restrict__ W1, const float* __restrict__ b1,
                    const float* __restrict__ g1, const float* __restrict__ be1,
                    const float* __restrict__ W2, const float* __restrict__ b2,
                    const float* __restrict__ g2, const float* __restrict__ be2,
                    const float* __restrict__ W3, const float* __restrict__ b3,
                    float* __restrict__ out, int E)
{
    extern __shared__ char smc[];
    const int tid = threadIdx.x;

    // ---- stage weights (fp16, k-permuted); params (f32) ----
    for (int i = tid; i < 64 * 144; i += NTHREADS) {
        const int n = i / 144, k = i % 144;
        const int c = k >> 4, r = k & 15;
        const int pos = (r < 8) ? (c * 16 + (r >> 1) * 4 + (r & 1))
                                : (c * 16 + ((r - 8) >> 1) * 4 + 2 + (r & 1));
        reinterpret_cast<__half*>(smc + oW1)[n * 144 + pos] = __float2half_rn(W1[k * 64 + n]);
    }
    for (int i = tid; i < 64 * 64; i += NTHREADS) {
        const int n = i >> 6, k = i & 63;
        const int c = k >> 4, r = k & 15;
        const int pos = (r < 8) ? (c * 16 + (r >> 1) * 4 + (r & 1))
                                : (c * 16 + ((r - 8) >> 1) * 4 + 2 + (r & 1));
        reinterpret_cast<__half*>(smc + oW2)[n * 80 + pos] = __float2half_rn(W2[k * 64 + n]);
    }
    float* P = reinterpret_cast<float*>(smc + oP);
    if (tid < 64) {
        P[tid]       = b1[tid];  P[64 + tid]  = g1[tid];  P[128 + tid] = be1[tid];
        P[192 + tid] = b2[tid];  P[256 + tid] = g2[tid];  P[320 + tid] = be2[tid];
        P[384 + tid] = W3[tid];
    }
    if (tid == 0) P[448] = b3[0];
    __syncthreads();

    const int warp = tid >> 5, lane = tid & 31;
    const int g = lane >> 2, tg = lane & 3;
    char* const Aw = smc + oA + warp * 32 * RSA;           // warp-private 32-row slice
    const char* const Ath = Aw + g * RSA + tg * 8;         // thread's fragment base
    const char* const B1th = smc + oW1 + g * RSA + tg * 8;
    const char* const B2th = smc + oW2 + g * RSW2 + tg * 8;

    const int nChunks = (E + 31) / 32;

    for (int ch = blockIdx.x * NW + warp; ch < nChunks; ch += gridDim.x * NW) {
        const int base = ch * 32;
        const int e = base + lane;

        int si = 0, di = 0;
        if (e < E) {
            si = eidx[e];
            di = eidx[(size_t)E + e];
        }

        __syncwarp();   // prior iteration's H reads done before overwrite

        // ---------------- phase A: gather src features (k 0..63) ----------------
        gather_nodes<PRE>(Aw, nodef, si, base, E, lane);
        __syncwarp();

        float acc[2][8][4];
        #pragma unroll
        for (int mt = 0; mt < 2; mt++)
            #pragma unroll
            for (int nf = 0; nf < 8; nf++)
                acc[mt][nf][0] = acc[mt][nf][1] = acc[mt][nf][2] = acc[mt][nf][3] = 0.f;

        // GEMM1 phase A: buffer chunks 0..3 <-> W1 chunks 0..3
        gemm_f16<4>(acc, Ath, B1th, 0, RSA);
        __syncwarp();

        // ---------------- phase B: gather dst (buf k 0..63) + eattr (buf chunk 4) ----------------
        gather_nodes<PRE>(Aw, nodef, di, base, E, lane);
        {
            const int rsub = lane >> 2;
            const int m = lane & 3;
            const int off1 = 128 + pair_base(m);     // buffer chunk 4
            #pragma unroll
            for (int it = 0; it < 4; it++) {
                const int row = it * 8 + rsub;
                unsigned o0 = 0u, o1 = 0u;
                if (base + row < E) {
                    float4 v = *reinterpret_cast<const float4*>(eattr + (size_t)(base + row) * 16 + m * 4);
                    o0 = packh2(v.x, v.y);
                    o1 = packh2(v.z, v.w);
                }
                char* rp = Aw + row * RSA;
                *reinterpret_cast<unsigned*>(rp + off1)     = o0;
                *reinterpret_cast<unsigned*>(rp + off1 + 8) = o1;
            }
        }
        __syncwarp();

        // GEMM1 phase B: buffer chunks 0..4 <-> W1 chunks 4..8
        gemm_f16<5>(acc, Ath, B1th, 4, RSA);
        __syncwarp();

        // ---------------- bias + LN1 + LeakyReLU -> H (fp16, buffer chunks 0..3) ----------------
        {
            float s[4] = {0.f, 0.f, 0.f, 0.f}, q[4] = {0.f, 0.f, 0.f, 0.f};
            #pragma unroll
            for (int mt = 0; mt < 2; mt++)
                #pragma unroll
                for (int nf = 0; nf < 8; nf++) {
                    const int col = nf * 8 + tg * 2;
                    const float bc0 = P[col], bc1 = P[col + 1];
                    float* a = acc[mt][nf];
                    a[0] += bc0; a[1] += bc1; a[2] += bc0; a[3] += bc1;
                    s[mt * 2]     += a[0] + a[1];
                    q[mt * 2]     += a[0] * a[0] + a[1] * a[1];
                    s[mt * 2 + 1] += a[2] + a[3];
                    q[mt * 2 + 1] += a[2] * a[2] + a[3] * a[3];
                }
            float mu[4], is[4];
            #pragma unroll
            for (int r = 0; r < 4; r++) {
                s[r] += __shfl_xor_sync(0xffffffffu, s[r], 1);
                s[r] += __shfl_xor_sync(0xffffffffu, s[r], 2);
                q[r] += __shfl_xor_sync(0xffffffffu, q[r], 1);
                q[r] += __shfl_xor_sync(0xffffffffu, q[r], 2);
                mu[r] = s[r] * (1.f / HID);
                is[r] = rsqrtf(fmaxf(q[r] * (1.f / HID) - mu[r] * mu[r], 0.f) + 1e-5f);
            }
            #pragma unroll
            for (int mt = 0; mt < 2; mt++) {
                char* h0p = Aw + (g + mt * 16) * RSA;
                char* h1p = Aw + (g + 8 + mt * 16) * RSA;
                const float mu0 = mu[mt * 2], is0 = is[mt * 2];
                const float mu1 = mu[mt * 2 + 1], is1 = is[mt * 2 + 1];
                #pragma unroll
                for (int nf = 0; nf < 8; nf++) {
                    const int col = nf * 8 + tg * 2;
                    const float ga0 = P[64 + col],  ga1 = P[64 + col + 1];
                    const float bb0 = P[128 + col], bb1 = P[128 + col + 1];
                    const float* a = acc[mt][nf];
                    float h00 = (a[0] - mu0) * is0 * ga0 + bb0;
                    float h01 = (a[1] - mu0) * is0 * ga1 + bb1;
                    float h10 = (a[2] - mu1) * is1 * ga0 + bb0;
                    float h11 = (a[3] - mu1) * is1 * ga1 + bb1;
                    h00 = h00 < 0.f ? 0.1f * h00 : h00;
                    h01 = h01 < 0.f ? 0.1f * h01 : h01;
                    h10 = h10 < 0.f ? 0.1f * h10 : h10;
                    h11 = h11 < 0.f ? 0.1f * h11 : h11;
                    const int off = (nf >> 1) * 32 + tg * 8 + (nf & 1) * 4;
                    *reinterpret_cast<unsigned*>(h0p + off) = packh2(h00, h01);
                    *reinterpret_cast<unsigned*>(h1p + off) = packh2(h10, h11);
                }
            }
        }
        __syncwarp();

        // ---------------- GEMM2: buffer chunks 0..3 <-> W2 chunks 0..3 ----------------
        #pragma unroll
        for (int mt = 0; mt < 2; mt++)
            #pragma unroll
            for (int nf = 0; nf < 8; nf++)
                acc[mt][nf][0] = acc[mt][nf][1] = acc[mt][nf][2] = acc[mt][nf][3] = 0.f;
        gemm_f16<4>(acc, Ath, B2th, 0, RSW2);

        // ---------------- bias + LN2 + LeakyReLU + layer3 dot -> out ----------------
        {
            float s[4] = {0.f, 0.f, 0.f, 0.f}, q[4] = {0.f, 0.f, 0.f, 0.f};
            #pragma unroll
            for (int mt = 0; mt < 2; mt++)
                #pragma unroll
                for (int nf = 0; nf < 8; nf++) {
                    const int col = nf * 8 + tg * 2;
                    const float bc0 = P[192 + col], bc1 = P[192 + col + 1];
                    float* a = acc[mt][nf];
                    a[0] += bc0; a[1] += bc1; a[2] += bc0; a[3] += bc1;
                    s[mt * 2]     += a[0] + a[1];
                    q[mt * 2]     += a[0] * a[0] + a[1] * a[1];
                    s[mt * 2 + 1] += a[2] + a[3];
                    q[mt * 2 + 1] += a[2] * a[2] + a[3] * a[3];
                }
            float mu[4], is[4];
            #pragma unroll
            for (int r = 0; r < 4; r++) {
                s[r] += __shfl_xor_sync(0xffffffffu, s[r], 1);
                s[r] += __shfl_xor_sync(0xffffffffu, s[r], 2);
                q[r] += __shfl_xor_sync(0xffffffffu, q[r], 1);
                q[r] += __shfl_xor_sync(0xffffffffu, q[r], 2);
                mu[r] = s[r] * (1.f / HID);
                is[r] = rsqrtf(fmaxf(q[r] * (1.f / HID) - mu[r] * mu[r], 0.f) + 1e-5f);
            }
            float y[4] = {0.f, 0.f, 0.f, 0.f};
            #pragma unroll
            for (int mt = 0; mt < 2; mt++)
                #pragma unroll
                for (int nf = 0; nf < 8; nf++) {
                    const int col = nf * 8 + tg * 2;
                    const float ga0 = P[256 + col], ga1 = P[256 + col + 1];
                    const float bb0 = P[320 + col], bb1 = P[320 + col + 1];
                    const float w30 = P[384 + col], w31 = P[384 + col + 1];
                    const float* a = acc[mt][nf];
                    float h00 = (a[0] - mu[mt * 2]) * is[mt * 2] * ga0 + bb0;
                    float h01 = (a[1] - mu[mt * 2]) * is[mt * 2] * ga1 + bb1;
                    float h10 = (a[2] - mu[mt * 2 + 1]) * is[mt * 2 + 1] * ga0 + bb0;
                    float h11 = (a[3] - mu[mt * 2 + 1]) * is[mt * 2 + 1] * ga1 + bb1;
                    h00 = h00 < 0.f ? 0.1f * h00 : h00;
                    h01 = h01 < 0.f ? 0.1f * h01 : h01;
                    h10 = h10 < 0.f ? 0.1f * h10 : h10;
                    h11 = h11 < 0.f ? 0.1f * h11 : h11;
                    y[mt * 2]     += h00 * w30 + h01 * w31;
                    y[mt * 2 + 1] += h10 * w30 + h11 * w31;
                }
            #pragma unroll
            for (int r = 0; r < 4; r++) {
                y[r] += __shfl_xor_sync(0xffffffffu, y[r], 1);
                y[r] += __shfl_xor_sync(0xffffffffu, y[r], 2);
            }
            if (tg == 0) {
                const float b3s = P[448];
                #pragma unroll
                for (int r = 0; r < 4; r++) {
                    const int eo = base + g + ((r & 1) ? 8 : 0) + ((r >> 1) ? 16 : 0);
                    if (eo < E) out[eo] = y[r] + b3s;
                }
            }
        }
    }
}

extern "C" void kernel_launch(void* const* d_in, const int* in_sizes, int n_in,
                              void* d_out, int out_size) {
    const float* nodef = (const float*)d_in[0];
    const int*   eidx  = (const int*)d_in[1];
    const float* eattr = (const float*)d_in[2];
    const float* W1 = (const float*)d_in[3];
    const float* b1 = (const float*)d_in[4];
    const float* g1 = (const float*)d_in[5];
    const float* be1 = (const float*)d_in[6];
    const float* W2 = (const float*)d_in[7];
    const float* b2 = (const float*)d_in[8];
    const float* g2 = (const float*)d_in[9];
    const float* be2 = (const float*)d_in[10];
    const float* W3 = (const float*)d_in[11];
    const float* b3 = (const float*)d_in[12];
    float* out = (float*)d_out;

    const int E = out_size;
    if (E <= 0) return;

    int dev = 0;
    cudaGetDevice(&dev);
    int sms = 148;
    cudaDeviceGetAttribute(&sms, cudaDevAttrMultiProcessorCount, dev);

    const int nChunks = (E + 31) / 32;
    const int ctasNeeded = (nChunks + NW - 1) / NW;
    const int grid = (ctasNeeded < sms) ? ctasNeeded : sms;

    const int nodeElems = in_sizes[0];          // n_nodes * 64
    const bool pre = (nodeElems > 0) && (nodeElems <= MAX_NODE_ELEMS) && ((nodeElems & 3) == 0);

    if (pre) {
        const int n4 = nodeElems >> 2;
        int pgrid = (n4 + 255) / 256;
        if (pgrid > 2 * sms) pgrid = 2 * sms;
        conv_nodes_kernel<<<pgrid, 256>>>(reinterpret_cast<const float4*>(nodef), n4);

        cudaFuncSetAttribute(edgenet_kernel<true>, cudaFuncAttributeMaxDynamicSharedMemorySize, SMEM_BYTES);
        edgenet_kernel<true><<<grid, NTHREADS, SMEM_BYTES>>>(
            nodef, eidx, eattr, W1, b1, g1, be1, W2, b2, g2, be2, W3, b3, out, E);
    } else {
        cudaFuncSetAttribute(edgenet_kernel<false>, cudaFuncAttributeMaxDynamicSharedMemorySize, SMEM_BYTES);
        edgenet_kernel<false><<<grid, NTHREADS, SMEM_BYTES>>>(
            nodef, eidx, eattr, W1, b1, g1, be1, W2, b2, g2, be2, W3, b3, out, E);
    }
}